// round 16
// baseline (speedup 1.0000x reference)
#include <cuda_runtime.h>
#include <math.h>

// ---------------------------------------------------------------------------
// ZBLRepulsion: per-edge repulsion energy + segment_sum over receivers.
//   N_NODES = 1,000,000   N_EDGES = 32,000,000   N_SPECIES = 100
//
// Converged design + R16 PDL overlap:
//   prep : params (incl. p, ln d) + per-node z byte; zero output.
//          8 nodes/thread, 512-thr blocks. Each block fires
//          cudaTriggerProgrammaticLaunchCompletion() after its last write.
//   edge : launched with ProgrammaticStreamSerialization — CTAs start while
//          prep drains; they issue the 4 independent streaming LDG.128s,
//          then cudaGridDependencySynchronize() before touching g_params /
//          g_z4 / out. Body otherwise identical to the converged kernel:
//          4 edges/thread (32 regs / 64-warp occ), 8 batched random u8
//          z-gathers, MUFU d*z^p, early RED.ADD.
//
// Floor model (validated R3-R15): l1tex wavefronts bind — 64M random gather
// lanes + 32M spread REDG; L1~90% / L2~91% co-saturated. Edge kernel is at
// its floor (best sample 325.8us); the only remaining serial cost is the
// prep->edge launch gap (~4.5us), targeted here via PDL.
// ---------------------------------------------------------------------------

#define KE_CONST 14.399645351950548
#define MAX_NODES   1000000

__device__ float  g_params[10];                 // a0..3, c0..3(*KE/2), p, ln d
__device__ uchar4 g_z4[(MAX_NODES + 3) / 4];    // packed per-node z bytes

__device__ __forceinline__ float softplus_f(float x) {
    return fmaxf(x, 0.0f) + log1pf(expf(-fabsf(x)));
}

// ---- kernel 0: fused prep (params in block 0; z-pack + zero, 8/thread) ----
__global__ void __launch_bounds__(512)
zbl_prep_kernel(const float* __restrict__ a_raw,
                const float* __restrict__ c_raw,
                const float* __restrict__ p_raw,
                const float* __restrict__ d_raw,
                const int* __restrict__ index_to_z,
                const int* __restrict__ species,
                float* __restrict__ out,
                int n_nodes, int out_n) {
    if (blockIdx.x == 0 && threadIdx.x == 0) {
        float c[4], csum = 0.0f;
#pragma unroll
        for (int k = 0; k < 4; k++) {
            g_params[k] = softplus_f(a_raw[k]);
            c[k] = softplus_f(c_raw[k]);
            csum += c[k];
        }
        float scale = (float)(KE_CONST * 0.5) / csum;
#pragma unroll
        for (int k = 0; k < 4; k++) g_params[4 + k] = c[k] * scale;
        g_params[8] = softplus_f(p_raw[0]);
        g_params[9] = logf(softplus_f(d_raw[0]));   // ln d (d > 0 always)
    }

    int i = blockIdx.x * blockDim.x + threadIdx.x;
    long long base = (long long)i * 8;      // 8 nodes per thread

    // pack z = index_to_z[species] -> u8 (two uchar4 stores)
    if (base + 7 < n_nodes) {
        int4 s0 = *reinterpret_cast<const int4*>(species + base);
        int4 s1 = *reinterpret_cast<const int4*>(species + base + 4);
        g_z4[(base >> 2) + 0] = make_uchar4(
            (unsigned char)__ldg(index_to_z + s0.x),
            (unsigned char)__ldg(index_to_z + s0.y),
            (unsigned char)__ldg(index_to_z + s0.z),
            (unsigned char)__ldg(index_to_z + s0.w));
        g_z4[(base >> 2) + 1] = make_uchar4(
            (unsigned char)__ldg(index_to_z + s1.x),
            (unsigned char)__ldg(index_to_z + s1.y),
            (unsigned char)__ldg(index_to_z + s1.z),
            (unsigned char)__ldg(index_to_z + s1.w));
    } else if (base < n_nodes) {
        unsigned char* zp = reinterpret_cast<unsigned char*>(g_z4);
        for (long long k = base; k < n_nodes; k++)
            zp[k] = (unsigned char)index_to_z[species[k]];
    }

    // zero output (two float4 stores)
    if (base + 7 < out_n) {
        float4 z = make_float4(0.f, 0.f, 0.f, 0.f);
        *reinterpret_cast<float4*>(out + base)     = z;
        *reinterpret_cast<float4*>(out + base + 4) = z;
    } else if (base < out_n) {
        for (long long k = base; k < out_n; k++) out[k] = 0.0f;
    }

    // allow the PDL-dependent edge kernel to begin
    cudaTriggerProgrammaticLaunchCompletion();
}

// ---- per-edge math (z bytes in, no table) ---------------------------------
__device__ __forceinline__ float zbl_energy(float dd, float ct,
                                            unsigned int zjb, unsigned int zib,
                                            const float* __restrict__ P) {
    float zi = (float)zib;
    float zj = (float)zjb;

    float x = ct * zi * zj * __fdividef(1.0f, dd + 1e-8f);

    // d*z^p = exp(p*ln z + ln d)
    float zpi = __expf(fmaf(P[8], __logf(zi), P[9]));
    float zpj = __expf(fmaf(P[8], __logf(zj), P[9]));
    float rzd = dd * (zpi + zpj);

    float y = P[4] * __expf(-P[0] * rzd)
            + P[5] * __expf(-P[1] * rzd)
            + P[6] * __expf(-P[2] * rzd)
            + P[7] * __expf(-P[3] * rzd);

    float sd = dd * (1.0f / 1.5f);
    float e1 = __expf(-__fdividef(1.0f, fmaxf(sd, 1e-8f)));
    float e2 = __expf(-__fdividef(1.0f, fmaxf(1.0f - sd, 1e-8f)));
    float w  = __fdividef(e2, e1 + e2);

    return w * x * y;
}

// ---- kernel 1: edge loop, 4 edges/thread, early REDs, PDL-overlapped ------
__global__ void __launch_bounds__(256)
zbl_edge_kernel(const float* __restrict__ distances,
                const float* __restrict__ cutoffs,
                const int* __restrict__ senders,
                const int* __restrict__ receivers,
                float* __restrict__ out,
                int n_edges) {
    int i  = blockIdx.x * blockDim.x + threadIdx.x;
    long long e0 = (long long)i * 4;
    if (e0 >= n_edges) {
        cudaGridDependencySynchronize();
        return;
    }

    if (e0 + 3 < n_edges) {
        // streaming loads: independent of prep -> issue BEFORE the grid sync
        float4 d4 = __ldcg(reinterpret_cast<const float4*>(distances + e0));
        float4 c4 = __ldcg(reinterpret_cast<const float4*>(cutoffs   + e0));
        int4   s4 = __ldcg(reinterpret_cast<const int4*>(senders    + e0));
        int4   r4 = __ldcg(reinterpret_cast<const int4*>(receivers  + e0));

        // wait for prep's writes (g_params, g_z4, zeroed out) to be visible
        cudaGridDependencySynchronize();

        float P[10];
#pragma unroll
        for (int k = 0; k < 10; k++) P[k] = g_params[k];
        const unsigned char* zb = reinterpret_cast<const unsigned char*>(g_z4);

        // all 8 gathers in flight before compute
        unsigned int sa = __ldg(zb + s4.x), ra = __ldg(zb + r4.x);
        unsigned int sb = __ldg(zb + s4.y), rb = __ldg(zb + r4.y);
        unsigned int sc = __ldg(zb + s4.z), rc = __ldg(zb + r4.z);
        unsigned int sd_ = __ldg(zb + s4.w), rd = __ldg(zb + r4.w);

        // compute + fire each RED as soon as its value is ready
        float va = zbl_energy(d4.x, c4.x, sa, ra, P);
        atomicAdd(out + r4.x, va);
        float vb = zbl_energy(d4.y, c4.y, sb, rb, P);
        atomicAdd(out + r4.y, vb);
        float vc = zbl_energy(d4.z, c4.z, sc, rc, P);
        atomicAdd(out + r4.z, vc);
        float vd = zbl_energy(d4.w, c4.w, sd_, rd, P);
        atomicAdd(out + r4.w, vd);
    } else {
        cudaGridDependencySynchronize();
        float P[10];
#pragma unroll
        for (int k = 0; k < 10; k++) P[k] = g_params[k];
        const unsigned char* zb = reinterpret_cast<const unsigned char*>(g_z4);
        for (long long e = e0; e < n_edges; e++) {
            unsigned int si = zb[senders[e]];
            unsigned int ri = zb[receivers[e]];
            float v = zbl_energy(distances[e], cutoffs[e], si, ri, P);
            atomicAdd(out + receivers[e], v);
        }
    }
}

// ---------------------------------------------------------------------------
extern "C" void kernel_launch(void* const* d_in, const int* in_sizes, int n_in,
                              void* d_out, int out_size) {
    const int*   node_species = (const int*)  d_in[0];
    const float* distances    = (const float*)d_in[1];
    const float* cutoffs      = (const float*)d_in[2];
    const int*   senders      = (const int*)  d_in[3];
    const int*   receivers    = (const int*)  d_in[4];
    const int*   index_to_z   = (const int*)  d_in[5];
    const float* a_raw        = (const float*)d_in[6];
    const float* c_raw        = (const float*)d_in[7];
    const float* p_raw        = (const float*)d_in[8];
    const float* d_raw        = (const float*)d_in[9];

    int n_nodes = in_sizes[0];
    int n_edges = in_sizes[1];
    float* out  = (float*)d_out;

    {
        int n = (n_nodes > out_size) ? n_nodes : out_size;
        long long octs = ((long long)n + 7) / 8;
        int threads = 512;
        int blocks  = (int)((octs + threads - 1) / threads);
        zbl_prep_kernel<<<blocks, threads>>>(a_raw, c_raw, p_raw, d_raw,
                                             index_to_z, node_species, out,
                                             n_nodes, out_size);
    }

    {
        int threads = 256;
        long long quads = ((long long)n_edges + 3) / 4;
        int blocks  = (int)((quads + threads - 1) / threads);

        cudaLaunchConfig_t cfg = {};
        cfg.gridDim  = dim3((unsigned)blocks, 1, 1);
        cfg.blockDim = dim3((unsigned)threads, 1, 1);
        cfg.dynamicSmemBytes = 0;
        cfg.stream = 0;
        cudaLaunchAttribute attrs[1];
        attrs[0].id = cudaLaunchAttributeProgrammaticStreamSerialization;
        attrs[0].val.programmaticStreamSerializationAllowed = 1;
        cfg.attrs = attrs;
        cfg.numAttrs = 1;

        cudaLaunchKernelEx(&cfg, zbl_edge_kernel,
                           distances, cutoffs, senders, receivers,
                           out, n_edges);
    }
}

// round 17
// speedup vs baseline: 1.0134x; 1.0134x over previous
#include <cuda_runtime.h>
#include <math.h>

// ---------------------------------------------------------------------------
// ZBLRepulsion: per-edge repulsion energy + segment_sum over receivers.
//   N_NODES = 1,000,000   N_EDGES = 32,000,000   N_SPECIES = 100
//
// Converged design + PDL overlap (R17: sync-at-top variant):
//   prep : params (incl. p, ln d) + per-node z byte; zero output.
//          8 nodes/thread, 512-thr blocks; fires
//          cudaTriggerProgrammaticLaunchCompletion() after its last write.
//   edge : ProgrammaticStreamSerialization launch; CTAs start during prep's
//          drain and overlap launch ramp / reg alloc / I$ warm-up with it.
//          cudaGridDependencySynchronize() at the VERY TOP — no values live
//          across the sync, so the body keeps the proven 32-reg / 64-warp
//          configuration (R16's pre-sync loads cost regs 32->40, occ ->68%).
//          Body: 4 edges/thread, float4/int4 L2-stream loads, 8 batched
//          random u8 z-gathers, MUFU d*z^p, early RED.ADD.
//
// Floor model (validated R3-R16): l1tex wavefronts bind — 64M random gather
// lanes + 32M spread REDG; L1~90% / L2~91% co-saturated; edge floor
// ~326-334us. PDL gap measured: 4.5us -> 1.8us.
// ---------------------------------------------------------------------------

#define KE_CONST 14.399645351950548
#define MAX_NODES   1000000

__device__ float  g_params[10];                 // a0..3, c0..3(*KE/2), p, ln d
__device__ uchar4 g_z4[(MAX_NODES + 3) / 4];    // packed per-node z bytes

__device__ __forceinline__ float softplus_f(float x) {
    return fmaxf(x, 0.0f) + log1pf(expf(-fabsf(x)));
}

// ---- kernel 0: fused prep (params in block 0; z-pack + zero, 8/thread) ----
__global__ void __launch_bounds__(512)
zbl_prep_kernel(const float* __restrict__ a_raw,
                const float* __restrict__ c_raw,
                const float* __restrict__ p_raw,
                const float* __restrict__ d_raw,
                const int* __restrict__ index_to_z,
                const int* __restrict__ species,
                float* __restrict__ out,
                int n_nodes, int out_n) {
    if (blockIdx.x == 0 && threadIdx.x == 0) {
        float c[4], csum = 0.0f;
#pragma unroll
        for (int k = 0; k < 4; k++) {
            g_params[k] = softplus_f(a_raw[k]);
            c[k] = softplus_f(c_raw[k]);
            csum += c[k];
        }
        float scale = (float)(KE_CONST * 0.5) / csum;
#pragma unroll
        for (int k = 0; k < 4; k++) g_params[4 + k] = c[k] * scale;
        g_params[8] = softplus_f(p_raw[0]);
        g_params[9] = logf(softplus_f(d_raw[0]));   // ln d (d > 0 always)
    }

    int i = blockIdx.x * blockDim.x + threadIdx.x;
    long long base = (long long)i * 8;      // 8 nodes per thread

    // pack z = index_to_z[species] -> u8 (two uchar4 stores)
    if (base + 7 < n_nodes) {
        int4 s0 = *reinterpret_cast<const int4*>(species + base);
        int4 s1 = *reinterpret_cast<const int4*>(species + base + 4);
        g_z4[(base >> 2) + 0] = make_uchar4(
            (unsigned char)__ldg(index_to_z + s0.x),
            (unsigned char)__ldg(index_to_z + s0.y),
            (unsigned char)__ldg(index_to_z + s0.z),
            (unsigned char)__ldg(index_to_z + s0.w));
        g_z4[(base >> 2) + 1] = make_uchar4(
            (unsigned char)__ldg(index_to_z + s1.x),
            (unsigned char)__ldg(index_to_z + s1.y),
            (unsigned char)__ldg(index_to_z + s1.z),
            (unsigned char)__ldg(index_to_z + s1.w));
    } else if (base < n_nodes) {
        unsigned char* zp = reinterpret_cast<unsigned char*>(g_z4);
        for (long long k = base; k < n_nodes; k++)
            zp[k] = (unsigned char)index_to_z[species[k]];
    }

    // zero output (two float4 stores)
    if (base + 7 < out_n) {
        float4 z = make_float4(0.f, 0.f, 0.f, 0.f);
        *reinterpret_cast<float4*>(out + base)     = z;
        *reinterpret_cast<float4*>(out + base + 4) = z;
    } else if (base < out_n) {
        for (long long k = base; k < out_n; k++) out[k] = 0.0f;
    }

    // allow the PDL-dependent edge kernel to begin
    cudaTriggerProgrammaticLaunchCompletion();
}

// ---- per-edge math (z bytes in, no table) ---------------------------------
__device__ __forceinline__ float zbl_energy(float dd, float ct,
                                            unsigned int zjb, unsigned int zib,
                                            const float* __restrict__ P) {
    float zi = (float)zib;
    float zj = (float)zjb;

    float x = ct * zi * zj * __fdividef(1.0f, dd + 1e-8f);

    // d*z^p = exp(p*ln z + ln d)
    float zpi = __expf(fmaf(P[8], __logf(zi), P[9]));
    float zpj = __expf(fmaf(P[8], __logf(zj), P[9]));
    float rzd = dd * (zpi + zpj);

    float y = P[4] * __expf(-P[0] * rzd)
            + P[5] * __expf(-P[1] * rzd)
            + P[6] * __expf(-P[2] * rzd)
            + P[7] * __expf(-P[3] * rzd);

    float sd = dd * (1.0f / 1.5f);
    float e1 = __expf(-__fdividef(1.0f, fmaxf(sd, 1e-8f)));
    float e2 = __expf(-__fdividef(1.0f, fmaxf(1.0f - sd, 1e-8f)));
    float w  = __fdividef(e2, e1 + e2);

    return w * x * y;
}

// ---- kernel 1: edge loop, 4 edges/thread, early REDs, PDL sync-at-top -----
__global__ void __launch_bounds__(256)
zbl_edge_kernel(const float* __restrict__ distances,
                const float* __restrict__ cutoffs,
                const int* __restrict__ senders,
                const int* __restrict__ receivers,
                float* __restrict__ out,
                int n_edges) {
    // wait for prep's writes; nothing live across this -> 32-reg body
    cudaGridDependencySynchronize();

    float P[10];
#pragma unroll
    for (int k = 0; k < 10; k++) P[k] = g_params[k];

    const unsigned char* zb = reinterpret_cast<const unsigned char*>(g_z4);

    int i  = blockIdx.x * blockDim.x + threadIdx.x;
    long long e0 = (long long)i * 4;
    if (e0 >= n_edges) return;

    if (e0 + 3 < n_edges) {
        // streaming loads: L2-only, keep L1 for the z gathers
        float4 d4 = __ldcg(reinterpret_cast<const float4*>(distances + e0));
        float4 c4 = __ldcg(reinterpret_cast<const float4*>(cutoffs   + e0));
        int4   s4 = __ldcg(reinterpret_cast<const int4*>(senders    + e0));
        int4   r4 = __ldcg(reinterpret_cast<const int4*>(receivers  + e0));

        // all 8 gathers in flight before compute
        unsigned int sa = __ldg(zb + s4.x), ra = __ldg(zb + r4.x);
        unsigned int sb = __ldg(zb + s4.y), rb = __ldg(zb + r4.y);
        unsigned int sc = __ldg(zb + s4.z), rc = __ldg(zb + r4.z);
        unsigned int sd_ = __ldg(zb + s4.w), rd = __ldg(zb + r4.w);

        // compute + fire each RED as soon as its value is ready
        float va = zbl_energy(d4.x, c4.x, sa, ra, P);
        atomicAdd(out + r4.x, va);
        float vb = zbl_energy(d4.y, c4.y, sb, rb, P);
        atomicAdd(out + r4.y, vb);
        float vc = zbl_energy(d4.z, c4.z, sc, rc, P);
        atomicAdd(out + r4.z, vc);
        float vd = zbl_energy(d4.w, c4.w, sd_, rd, P);
        atomicAdd(out + r4.w, vd);
    } else {
        for (long long e = e0; e < n_edges; e++) {
            unsigned int si = zb[senders[e]];
            unsigned int ri = zb[receivers[e]];
            float v = zbl_energy(distances[e], cutoffs[e], si, ri, P);
            atomicAdd(out + receivers[e], v);
        }
    }
}

// ---------------------------------------------------------------------------
extern "C" void kernel_launch(void* const* d_in, const int* in_sizes, int n_in,
                              void* d_out, int out_size) {
    const int*   node_species = (const int*)  d_in[0];
    const float* distances    = (const float*)d_in[1];
    const float* cutoffs      = (const float*)d_in[2];
    const int*   senders      = (const int*)  d_in[3];
    const int*   receivers    = (const int*)  d_in[4];
    const int*   index_to_z   = (const int*)  d_in[5];
    const float* a_raw        = (const float*)d_in[6];
    const float* c_raw        = (const float*)d_in[7];
    const float* p_raw        = (const float*)d_in[8];
    const float* d_raw        = (const float*)d_in[9];

    int n_nodes = in_sizes[0];
    int n_edges = in_sizes[1];
    float* out  = (float*)d_out;

    {
        int n = (n_nodes > out_size) ? n_nodes : out_size;
        long long octs = ((long long)n + 7) / 8;
        int threads = 512;
        int blocks  = (int)((octs + threads - 1) / threads);
        zbl_prep_kernel<<<blocks, threads>>>(a_raw, c_raw, p_raw, d_raw,
                                             index_to_z, node_species, out,
                                             n_nodes, out_size);
    }

    {
        int threads = 256;
        long long quads = ((long long)n_edges + 3) / 4;
        int blocks  = (int)((quads + threads - 1) / threads);

        cudaLaunchConfig_t cfg = {};
        cfg.gridDim  = dim3((unsigned)blocks, 1, 1);
        cfg.blockDim = dim3((unsigned)threads, 1, 1);
        cfg.dynamicSmemBytes = 0;
        cfg.stream = 0;
        cudaLaunchAttribute attrs[1];
        attrs[0].id = cudaLaunchAttributeProgrammaticStreamSerialization;
        attrs[0].val.programmaticStreamSerializationAllowed = 1;
        cfg.attrs = attrs;
        cfg.numAttrs = 1;

        cudaLaunchKernelEx(&cfg, zbl_edge_kernel,
                           distances, cutoffs, senders, receivers,
                           out, n_edges);
    }
}